// round 9
// baseline (speedup 1.0000x reference)
#include <cuda_runtime.h>
#include <cuda_bf16.h>
#include <mma.h>
#include <math.h>

using namespace nvcuda;

#define NATOMS 25000
#define NEDGES 300000
#define NGRAPH 500
#define DDIM   256
#define ADIM   200
#define LLAYERS 3
#define TE     64      // rows per wmma block tile
#define NT     256     // threads per wmma block (8 warps: 4 M x 2 N)
#define LDA    272     // bf16 X row stride (544B, 32B-mult)
#define LDB    272     // bf16 B chunk row stride
#define LDF    72      // fp32 staging row stride (quarter = 64 cols + pad)
#define KCH    16      // K chunk per step

#define COEF_F ((float)(1.602176634e-19 * 1.602176634e-19 / \
                 (4.0 * 3.14159265358979323846 * 8.8541878128e-12 * 1e-10)))

typedef unsigned long long u64;

// smem layout (dynamic): Xh[64*272] Xl[64*272] | Bh[16*272] Bl[16*272] | F[64*72] f32
#define SM_XL   (64 * LDA)                 // 17408 bf16
#define SM_BOFF (2 * SM_XL * 2)            // 69632 bytes
#define SM_BL   (KCH * LDB)                // 4352 bf16
#define SM_FOFF (SM_BOFF + 2 * SM_BL * 2)  // 87040 bytes
#define SMEM_W  (SM_FOFF + 64 * LDF * 4)   // 105472 bytes

// ---- scratch (static device globals; no allocation) ----
__device__ float d_dist[NEDGES];
__device__ float d_h   [NATOMS * DDIM];
__device__ float d_hsrc[NATOMS * DDIM];
__device__ float d_hdst[NATOMS * DDIM];
__device__ float d_agg [NATOMS * DDIM];
__device__ float d_pool[NGRAPH];
__device__ int   d_cnt [NGRAPH];

// bf16-split weights, prepped once per launch. [L*4][256][256] row-major (k, n)
#define WELEMS (LLAYERS * 4 * DDIM * DDIM)
__device__ __align__(256) __nv_bfloat16 d_w1h[WELEMS];
__device__ __align__(256) __nv_bfloat16 d_w1l[WELEMS];
__device__ __align__(256) __nv_bfloat16 d_w2h[WELEMS];
__device__ __align__(256) __nv_bfloat16 d_w2l[WELEMS];

// ---- helpers ----
__device__ __forceinline__ void bsplit(float v, __nv_bfloat16& h, __nv_bfloat16& l) {
    h = __float2bfloat16(v);
    l = __float2bfloat16(v - __bfloat162float(h));
}
__device__ __forceinline__ void red2(float* p, float a, float b) {
    asm volatile("red.global.add.v2.f32 [%0], {%1, %2};" :: "l"(p), "f"(a), "f"(b) : "memory");
}
__device__ __forceinline__ float softplus_f(float x) {
    return fmaxf(x, 0.0f) + __logf(1.0f + __expf(-fabsf(x)));
}
__device__ __forceinline__ float mish_f(float x) {
    float ex = __expf(fminf(x, 20.0f));
    float p  = 1.0f + ex;
    float p2 = p * p;
    return x * __fdividef(p2 - 1.0f, p2 + 1.0f);
}

// ---- weight prep: fp32 -> (hi, lo) bf16 split ----
__global__ void __launch_bounds__(256) prep_w(const float* __restrict__ cw1,
                                              const float* __restrict__ cw2) {
    int i = blockIdx.x * blockDim.x + threadIdx.x;
    if (i < WELEMS) {
        __nv_bfloat16 h, l;
        bsplit(cw1[i], h, l); d_w1h[i] = h; d_w1l[i] = l;
        bsplit(cw2[i], h, l); d_w2h[i] = h; d_w2l[i] = l;
    }
}

// ---- cooperative B chunk load: 16 rows x 256 cols, both halves ----
__device__ __forceinline__ void ldB(__nv_bfloat16* sBh, __nv_bfloat16* sBl,
                                    const __nv_bfloat16* __restrict__ gWh,
                                    const __nv_bfloat16* __restrict__ gWl,
                                    int k0, int tid) {
    int rr = tid >> 4;             // 0..15
    int cb = (tid & 15) * 16;      // 0,16,..,240
    const uint4* sh = (const uint4*)(gWh + (size_t)(k0 + rr) * DDIM + cb);
    const uint4* sl = (const uint4*)(gWl + (size_t)(k0 + rr) * DDIM + cb);
    uint4* dh = (uint4*)(sBh + rr * LDB + cb);
    uint4* dl = (uint4*)(sBl + rr * LDB + cb);
    dh[0] = sh[0]; dh[1] = sh[1];
    dl[0] = sl[0]; dl[1] = sl[1];
}

// ---- wmma GEMM: D[64,256] = X[64,256] @ W[256,256], 3-pass bf16 split ----
__device__ __forceinline__ void wgemm(
    const __nv_bfloat16* __restrict__ gWh, const __nv_bfloat16* __restrict__ gWl,
    const __nv_bfloat16* sXh, const __nv_bfloat16* sXl,
    __nv_bfloat16* sBh, __nv_bfloat16* sBl,
    wmma::fragment<wmma::accumulator, 16, 16, 16, float>* acc,
    int tid, int mw, int nh) {
#pragma unroll
    for (int f = 0; f < 8; f++) wmma::fill_fragment(acc[f], 0.0f);
    for (int k0 = 0; k0 < DDIM; k0 += KCH) {
        __syncthreads();                       // B buffer free, X writes visible
        ldB(sBh, sBl, gWh, gWl, k0, tid);
        __syncthreads();
        wmma::fragment<wmma::matrix_a, 16, 16, 16, __nv_bfloat16, wmma::row_major> ah, al;
        wmma::load_matrix_sync(ah, sXh + mw * 16 * LDA + k0, LDA);
        wmma::load_matrix_sync(al, sXl + mw * 16 * LDA + k0, LDA);
#pragma unroll
        for (int f = 0; f < 8; f++) {
            wmma::fragment<wmma::matrix_b, 16, 16, 16, __nv_bfloat16, wmma::row_major> bh, bl;
            wmma::load_matrix_sync(bh, sBh + nh * 128 + f * 16, LDB);
            wmma::load_matrix_sync(bl, sBl + nh * 128 + f * 16, LDB);
            wmma::mma_sync(acc[f], ah, bh, acc[f]);
            wmma::mma_sync(acc[f], ah, bl, acc[f]);
            wmma::mma_sync(acc[f], al, bh, acc[f]);
        }
    }
    __syncthreads();
}

// Store one 64-col quarter of acc into fp32 staging (owning warps only), then sync.
__device__ __forceinline__ void stage_quarter(
    float* sF, wmma::fragment<wmma::accumulator, 16, 16, 16, float>* acc,
    int q, int mw, int nh) {
    if (nh == (q >> 1)) {
        int fb = (q & 1) * 4;
#pragma unroll
        for (int ff = 0; ff < 4; ff++)
            wmma::store_matrix_sync(sF + mw * 16 * LDF + ff * 16, acc[fb + ff],
                                    LDF, wmma::mem_row_major);
    }
    __syncthreads();
}

// ---- small kernels ----
__global__ void __launch_bounds__(256) dist_kernel(const float* __restrict__ r) {
    int e = blockIdx.x * blockDim.x + threadIdx.x;
    if (e < NEDGES) {
        float x = r[3 * e], y = r[3 * e + 1], z = r[3 * e + 2];
        d_dist[e] = sqrtf(x * x + y * y + z * z);
    }
}

__global__ void __launch_bounds__(256) zero_pool_kernel() {
    int g = blockIdx.x * blockDim.x + threadIdx.x;
    if (g < NGRAPH) { d_pool[g] = 0.0f; d_cnt[g] = 0; }
}

__global__ void __launch_bounds__(256) pool_kernel(const int* __restrict__ gids,
                                                   const float* __restrict__ out_w) {
    int warp = (blockIdx.x * blockDim.x + threadIdx.x) >> 5;
    int lane = threadIdx.x & 31;
    if (warp >= NATOMS) return;
    float s = 0.0f;
    for (int k = lane; k < DDIM; k += 32) {
        size_t off = (size_t)warp * DDIM + k;
        s += softplus_f(d_h[off] + d_agg[off]) * out_w[k];
    }
#pragma unroll
    for (int off = 16; off > 0; off >>= 1)
        s += __shfl_xor_sync(0xFFFFFFFFu, s, off);
    if (lane == 0) {
        atomicAdd(&d_pool[gids[warp]], s);
        atomicAdd(&d_cnt[gids[warp]], 1);
    }
}

__global__ void __launch_bounds__(256) final_kernel(const float* __restrict__ out_b,
                                                    float* __restrict__ out) {
    int g = blockIdx.x * blockDim.x + threadIdx.x;
    if (g < NGRAPH)
        out[g] = d_pool[g] / fmaxf((float)d_cnt[g], 1.0f) + out_b[0];
}

// ==== scalar embed path (proven; off critical path) ====
#define ETE   32
#define ENT   128
#define EPADR 36
#define KEMB  224
__device__ __forceinline__ u64 pack2f(float lo, float hi) {
    u64 v; asm("mov.b64 %0, {%1, %2};" : "=l"(v) : "f"(lo), "f"(hi)); return v;
}
__device__ __forceinline__ void unpack2f(u64 v, float& lo, float& hi) {
    asm("mov.b64 {%0, %1}, %2;" : "=f"(lo), "=f"(hi) : "l"(v));
}
__device__ __forceinline__ void fma2(u64& a, u64 x, u64 w) {
    asm("fma.rn.f32x2 %0, %1, %2, %0;" : "+l"(a) : "l"(x), "l"(w));
}
__device__ __forceinline__ void eldw4c(float2 w[4][2], const float* __restrict__ W,
                                       int k, int cp, int kmax) {
#pragma unroll
    for (int i = 0; i < 4; i++) {
        int kk = k + i; if (kk >= kmax) kk = kmax - 1;
        w[i][0] = *(const float2*)(W + (size_t)kk * DDIM + 2 * cp);
        w[i][1] = *(const float2*)(W + (size_t)kk * DDIM + 2 * cp + 128);
    }
}
__device__ __forceinline__ void eldx(ulonglong2 cur[4], const float* __restrict__ xs, int k) {
    const ulonglong2* xr = (const ulonglong2*)(xs + (size_t)k * EPADR);
#pragma unroll
    for (int j = 0; j < 4; j++) cur[j] = xr[j];
}
__device__ __forceinline__ void efma_k(u64 acc[32], float2 w01, float2 w23,
                                       const ulonglong2 cur[4]) {
    u64 wv0 = pack2f(w01.x, w01.x), wv1 = pack2f(w01.y, w01.y);
    u64 wv2 = pack2f(w23.x, w23.x), wv3 = pack2f(w23.y, w23.y);
#pragma unroll
    for (int j2 = 0; j2 < 4; j2++) {
        u64 plo = cur[j2].x, phi = cur[j2].y;
        fma2(acc[     2 * j2], plo, wv0); fma2(acc[     2 * j2 + 1], phi, wv0);
        fma2(acc[ 8 + 2 * j2], plo, wv1); fma2(acc[ 8 + 2 * j2 + 1], phi, wv1);
        fma2(acc[16 + 2 * j2], plo, wv2); fma2(acc[16 + 2 * j2 + 1], phi, wv2);
        fma2(acc[24 + 2 * j2], plo, wv3); fma2(acc[24 + 2 * j2 + 1], phi, wv3);
    }
}
__global__ void __launch_bounds__(ENT) embed_kernel(const int* __restrict__ atom_types,
                                                    const float* __restrict__ af,
                                                    const float* __restrict__ emb_w,
                                                    const float* __restrict__ emb_b) {
    extern __shared__ float esm[];
    float* xa = esm;
    __shared__ int sT[ETE];
    int tid = threadIdx.x;
    int cp = tid & 63, rg = tid >> 6, rbase = rg * 16;
    int row0 = blockIdx.x * ETE;
    if (tid < ETE) {
        int row = row0 + tid;
        sT[tid] = (row < NATOMS) ? atom_types[row] : 0;
    }
    __syncthreads();
    for (int idx = tid; idx < ETE * KEMB; idx += ENT) {
        int r = idx / KEMB, k = idx - r * KEMB;
        float v = 0.0f;
        if (k < ADIM && row0 + r < NATOMS) v = af[(size_t)sT[r] * ADIM + k];
        xa[k * EPADR + r] = v;
    }
    __syncthreads();
    u64 acc[32];
#pragma unroll
    for (int j = 0; j < 32; j++) acc[j] = 0ULL;
    {
        const float* xs = xa + rbase;
        float2 wa[4][2], wb[4][2];
        ulonglong2 cur[4], nxt[4];
        eldw4c(wa, emb_w, 0, cp, ADIM);
        eldx(cur, xs, 0);
        for (int k0 = 0; k0 < KEMB; k0 += 8) {
            eldw4c(wb, emb_w, k0 + 4, cp, ADIM);
#pragma unroll
            for (int i = 0; i < 4; i++) {
                int kk = k0 + i + 1; if (kk >= KEMB) kk = 0;
                eldx(nxt, xs, kk);
                efma_k(acc, wa[i][0], wa[i][1], cur);
#pragma unroll
                for (int j = 0; j < 4; j++) cur[j] = nxt[j];
            }
            eldw4c(wa, emb_w, (k0 + 8 < KEMB) ? k0 + 8 : 0, cp, ADIM);
#pragma unroll
            for (int i = 0; i < 4; i++) {
                int kk = k0 + 5 + i; if (kk >= KEMB) kk = 0;
                eldx(nxt, xs, kk);
                efma_k(acc, wb[i][0], wb[i][1], cur);
#pragma unroll
                for (int j = 0; j < 4; j++) cur[j] = nxt[j];
            }
        }
    }
    float2 b01 = *(const float2*)(emb_b + 2 * cp);
    float2 b23 = *(const float2*)(emb_b + 2 * cp + 128);
#pragma unroll
    for (int j = 0; j < 8; j++) {
        float lo0, hi0, lo1, hi1, lo2, hi2, lo3, hi3;
        unpack2f(acc[j],      lo0, hi0);
        unpack2f(acc[8 + j],  lo1, hi1);
        unpack2f(acc[16 + j], lo2, hi2);
        unpack2f(acc[24 + j], lo3, hi3);
        int r0 = row0 + rbase + 2 * j, r1 = r0 + 1;
        if (r0 < NATOMS) {
            *(float2*)(d_h + (size_t)r0 * DDIM + 2 * cp)       = make_float2(lo0 + b01.x, lo1 + b01.y);
            *(float2*)(d_h + (size_t)r0 * DDIM + 2 * cp + 128) = make_float2(lo2 + b23.x, lo3 + b23.y);
        }
        if (r1 < NATOMS) {
            *(float2*)(d_h + (size_t)r1 * DDIM + 2 * cp)       = make_float2(hi0 + b01.x, hi1 + b01.y);
            *(float2*)(d_h + (size_t)r1 * DDIM + 2 * cp + 128) = make_float2(hi2 + b23.x, hi3 + b23.y);
        }
    }
}

// ==== wmma node kernel: softplus update + zero agg, then src/dst MLPs ====
__global__ void __launch_bounds__(NT, 2) node_kernel_w(
    int l, int use_agg, const float* __restrict__ cb1, const float* __restrict__ cb2) {
    extern __shared__ char smem[];
    __nv_bfloat16* sXh = (__nv_bfloat16*)smem;
    __nv_bfloat16* sXl = sXh + SM_XL;
    __nv_bfloat16* sBh = (__nv_bfloat16*)(smem + SM_BOFF);
    __nv_bfloat16* sBl = sBh + SM_BL;
    float* sF = (float*)(smem + SM_FOFF);
    int tid = threadIdx.x;
    int wid = tid >> 5, mw = wid & 3, nh = wid >> 2;
    int row0 = blockIdx.x * TE;

    const size_t MM = (size_t)DDIM * DDIM;
    const __nv_bfloat16 *w1sh = d_w1h + (size_t)(l * 4 + 0) * MM, *w1sl = d_w1l + (size_t)(l * 4 + 0) * MM;
    const __nv_bfloat16 *w2sh = d_w2h + (size_t)(l * 4 + 0) * MM, *w2sl = d_w2l + (size_t)(l * 4 + 0) * MM;
    const __nv_bfloat16 *w1dh = d_w1h + (size_t)(l * 4 + 1) * MM, *w1dl = d_w1l + (size_t)(l * 4 + 1) * MM;
    const __nv_bfloat16 *w2dh = d_w2h + (size_t)(l * 4 + 1) * MM, *w2dl = d_w2l + (size_t)(l * 4 + 1) * MM;
    const float *b1s = cb1 + (l * 4 + 0) * DDIM, *b2s = cb2 + (l * 4 + 0) * DDIM;
    const float *b1d = cb1 + (l * 4 + 1) * DDIM, *b2d = cb2 + (l * 4 + 1) * DDIM;

    // load h tile (+ fused softplus/agg-zero), split to bf16
    for (int i = tid; i < TE * DDIM; i += NT) {
        int r = i >> 8, c = i & 255;
        int row = row0 + r;
        float v = 0.0f;
        if (row < NATOMS) {
            size_t off = (size_t)row * DDIM + c;
            if (use_agg) { v = softplus_f(d_h[off] + d_agg[off]); d_h[off] = v; }
            else v = d_h[off];
            d_agg[off] = 0.0f;
        }
        __nv_bfloat16 h, lo; bsplit(v, h, lo);
        sXh[r * LDA + c] = h; sXl[r * LDA + c] = lo;
    }

    wmma::fragment<wmma::accumulator, 16, 16, 16, float> acc[8];

    // src branch
    wgemm(w1sh, w1sl, sXh, sXl, sBh, sBl, acc, tid, mw, nh);
    for (int q = 0; q < 4; q++) {
        stage_quarter(sF, acc, q, mw, nh);
        for (int i = tid; i < 64 * 64; i += NT) {
            int r = i >> 6, c = i & 63; int C = q * 64 + c;
            float v = mish_f(sF[r * LDF + c] + b1s[C]);
            __nv_bfloat16 h, lo; bsplit(v, h, lo);
            sXh[r * LDA + C] = h; sXl[r * LDA + C] = lo;
        }
        __syncthreads();
    }
    wgemm(w2sh, w2sl, sXh, sXl, sBh, sBl, acc, tid, mw, nh);
    for (int q = 0; q < 4; q++) {
        stage_quarter(sF, acc, q, mw, nh);
        for (int i = tid; i < 64 * 64; i += NT) {
            int r = i >> 6, c = i & 63; int C = q * 64 + c;
            int row = row0 + r;
            if (row < NATOMS) d_hsrc[(size_t)row * DDIM + C] = sF[r * LDF + c] + b2s[C];
        }
        __syncthreads();
    }

    // reload h for dst branch (d_h updated above; sync makes it block-visible)
    for (int i = tid; i < TE * DDIM; i += NT) {
        int r = i >> 8, c = i & 255;
        int row = row0 + r;
        float v = (row < NATOMS) ? d_h[(size_t)row * DDIM + c] : 0.0f;
        __nv_bfloat16 h, lo; bsplit(v, h, lo);
        sXh[r * LDA + c] = h; sXl[r * LDA + c] = lo;
    }
    wgemm(w1dh, w1dl, sXh, sXl, sBh, sBl, acc, tid, mw, nh);
    for (int q = 0; q < 4; q++) {
        stage_quarter(sF, acc, q, mw, nh);
        for (int i = tid; i < 64 * 64; i += NT) {
            int r = i >> 6, c = i & 63; int C = q * 64 + c;
            float v = mish_f(sF[r * LDF + c] + b1d[C]);
            __nv_bfloat16 h, lo; bsplit(v, h, lo);
            sXh[r * LDA + C] = h; sXl[r * LDA + C] = lo;
        }
        __syncthreads();
    }
    wgemm(w2dh, w2dl, sXh, sXl, sBh, sBl, acc, tid, mw, nh);
    for (int q = 0; q < 4; q++) {
        stage_quarter(sF, acc, q, mw, nh);
        for (int i = tid; i < 64 * 64; i += NT) {
            int r = i >> 6, c = i & 63; int C = q * 64 + c;
            int row = row0 + r;
            if (row < NATOMS) d_hdst[(size_t)row * DDIM + C] = sF[r * LDF + c] + b2d[C];
        }
        __syncthreads();
    }
}

// ==== wmma edge kernel: RBF -> eMLP -> combine -> mMLP -> scatter ====
__global__ void __launch_bounds__(NT, 2) edge_kernel_w(
    const int* __restrict__ esrc, const int* __restrict__ edst, int l,
    const float* __restrict__ cb1, const float* __restrict__ cb2) {
    extern __shared__ char smem[];
    __nv_bfloat16* sXh = (__nv_bfloat16*)smem;
    __nv_bfloat16* sXl = sXh + SM_XL;
    __nv_bfloat16* sBh = (__nv_bfloat16*)(smem + SM_BOFF);
    __nv_bfloat16* sBl = sBh + SM_BL;
    float* sF = (float*)(smem + SM_FOFF);
    __shared__ int   sS[TE], sD[TE];
    __shared__ float sDist[TE];
    int tid = threadIdx.x;
    int wid = tid >> 5, mw = wid & 3, nh = wid >> 2;
    int e0 = blockIdx.x * TE;

    const size_t MM = (size_t)DDIM * DDIM;
    const __nv_bfloat16 *w1eh = d_w1h + (size_t)(l * 4 + 2) * MM, *w1el = d_w1l + (size_t)(l * 4 + 2) * MM;
    const __nv_bfloat16 *w2eh = d_w2h + (size_t)(l * 4 + 2) * MM, *w2el = d_w2l + (size_t)(l * 4 + 2) * MM;
    const __nv_bfloat16 *w1mh = d_w1h + (size_t)(l * 4 + 3) * MM, *w1ml = d_w1l + (size_t)(l * 4 + 3) * MM;
    const __nv_bfloat16 *w2mh = d_w2h + (size_t)(l * 4 + 3) * MM, *w2ml = d_w2l + (size_t)(l * 4 + 3) * MM;
    const float *b1e = cb1 + (l * 4 + 2) * DDIM, *b2e = cb2 + (l * 4 + 2) * DDIM;
    const float *b1m = cb1 + (l * 4 + 3) * DDIM, *b2m = cb2 + (l * 4 + 3) * DDIM;

    if (tid < TE) {
        int e = e0 + tid;
        sS[tid]    = (e < NEDGES) ? esrc[e] : 0;
        sD[tid]    = (e < NEDGES) ? edst[e] : 0;
        sDist[tid] = (e < NEDGES) ? d_dist[e] : 0.0f;
    }
    __syncthreads();

    // RBF -> X (bf16 split)
    for (int i = tid; i < TE * DDIM; i += NT) {
        int r = i >> 8, c = i & 255;
        float t = sDist[r] - (float)c * (1.0f / 255.0f);
        float v = __expf(-255.0f * t * t);
        __nv_bfloat16 h, lo; bsplit(v, h, lo);
        sXh[r * LDA + c] = h; sXl[r * LDA + c] = lo;
    }

    wmma::fragment<wmma::accumulator, 16, 16, 16, float> acc[8];

    // edge MLP layer 1: mish -> X
    wgemm(w1eh, w1el, sXh, sXl, sBh, sBl, acc, tid, mw, nh);
    for (int q = 0; q < 4; q++) {
        stage_quarter(sF, acc, q, mw, nh);
        for (int i = tid; i < 64 * 64; i += NT) {
            int r = i >> 6, c = i & 63; int C = q * 64 + c;
            float v = mish_f(sF[r * LDF + c] + b1e[C]);
            __nv_bfloat16 h, lo; bsplit(v, h, lo);
            sXh[r * LDA + C] = h; sXl[r * LDA + C] = lo;
        }
        __syncthreads();
    }

    // edge MLP layer 2 + Coulomb combine -> X
    wgemm(w2eh, w2el, sXh, sXl, sBh, sBl, acc, tid, mw, nh);
    for (int q = 0; q < 4; q++) {
        stage_quarter(sF, acc, q, mw, nh);
        for (int i = tid; i < 64 * 64; i += NT) {
            int r = i >> 6, c = i & 63; int C = q * 64 + c;
            float el = sF[r * LDF + c] + b2e[C];
            float hn = d_hsrc[(size_t)sS[r] * DDIM + C] *
                       d_hdst[(size_t)sD[r] * DDIM + C] * COEF_F;
            float v = __fdividef(hn, el);
            __nv_bfloat16 h, lo; bsplit(v, h, lo);
            sXh[r * LDA + C] = h; sXl[r * LDA + C] = lo;
        }
        __syncthreads();
    }

    // m MLP layer 1: mish -> X
    wgemm(w1mh, w1ml, sXh, sXl, sBh, sBl, acc, tid, mw, nh);
    for (int q = 0; q < 4; q++) {
        stage_quarter(sF, acc, q, mw, nh);
        for (int i = tid; i < 64 * 64; i += NT) {
            int r = i >> 6, c = i & 63; int C = q * 64 + c;
            float v = mish_f(sF[r * LDF + c] + b1m[C]);
            __nv_bfloat16 h, lo; bsplit(v, h, lo);
            sXh[r * LDA + C] = h; sXl[r * LDA + C] = lo;
        }
        __syncthreads();
    }

    // m MLP layer 2 + segment-sum scatter
    wgemm(w2mh, w2ml, sXh, sXl, sBh, sBl, acc, tid, mw, nh);
    for (int q = 0; q < 4; q++) {
        stage_quarter(sF, acc, q, mw, nh);
        for (int i = tid; i < 64 * 32; i += NT) {
            int r = i >> 5, c2 = i & 31; int C = q * 64 + 2 * c2;
            if (e0 + r < NEDGES) {
                float v0 = sF[r * LDF + 2 * c2]     + b2m[C];
                float v1 = sF[r * LDF + 2 * c2 + 1] + b2m[C + 1];
                red2(d_agg + (size_t)sD[r] * DDIM + C, v0, v1);
            }
        }
        __syncthreads();
    }
}

extern "C" void kernel_launch(void* const* d_in, const int* in_sizes, int n_in,
                              void* d_out, int out_size) {
    const int*   atom_types = (const int*)  d_in[0];
    const int*   esrc       = (const int*)  d_in[1];
    const int*   edst       = (const int*)  d_in[2];
    const int*   gids       = (const int*)  d_in[3];
    const float* r          = (const float*)d_in[4];
    const float* af         = (const float*)d_in[5];
    const float* emb_w      = (const float*)d_in[6];
    const float* emb_b      = (const float*)d_in[7];
    const float* cw1        = (const float*)d_in[8];
    const float* cb1        = (const float*)d_in[9];
    const float* cw2        = (const float*)d_in[10];
    const float* cb2        = (const float*)d_in[11];
    const float* out_w      = (const float*)d_in[12];
    const float* out_b      = (const float*)d_in[13];
    float* out = (float*)d_out;

    const int SMEM_EMBED = KEMB * EPADR * 4;
    cudaFuncSetAttribute(edge_kernel_w, cudaFuncAttributeMaxDynamicSharedMemorySize, SMEM_W);
    cudaFuncSetAttribute(node_kernel_w, cudaFuncAttributeMaxDynamicSharedMemorySize, SMEM_W);
    cudaFuncSetAttribute(embed_kernel,  cudaFuncAttributeMaxDynamicSharedMemorySize, SMEM_EMBED);

    dist_kernel<<<(NEDGES + 255) / 256, 256>>>(r);
    prep_w<<<(WELEMS + 255) / 256, 256>>>(cw1, cw2);
    embed_kernel<<<(NATOMS + ETE - 1) / ETE, ENT, SMEM_EMBED>>>(atom_types, af, emb_w, emb_b);

    for (int l = 0; l < LLAYERS; l++) {
        node_kernel_w<<<(NATOMS + TE - 1) / TE, NT, SMEM_W>>>(l, l > 0 ? 1 : 0, cb1, cb2);
        edge_kernel_w<<<(NEDGES + TE - 1) / TE, NT, SMEM_W>>>(esrc, edst, l, cb1, cb2);
    }

    zero_pool_kernel<<<(NGRAPH + 255) / 256, 256>>>();
    pool_kernel<<<(NATOMS * 32 + 255) / 256, 256>>>(gids, out_w);
    final_kernel<<<(NGRAPH + 255) / 256, 256>>>(out_b, out);
}

// round 10
// speedup vs baseline: 1.1920x; 1.1920x over previous
#include <cuda_runtime.h>
#include <cuda_bf16.h>
#include <mma.h>
#include <math.h>

using namespace nvcuda;

#define NATOMS 25000
#define NEDGES 300000
#define NGRAPH 500
#define DDIM   256
#define ADIM   200
#define LLAYERS 3
#define TE     64      // rows per wmma block tile
#define NT     256     // threads per wmma block (8 warps: 4 M x 2 N)
#define LDA    264     // bf16 X row stride (528B, 16B-mult)
#define LDB    264     // bf16 B chunk row stride
#define LDF    132     // fp32 staging row stride (half = 128 cols + pad)
#define KCH    16      // K chunk per step
#define NCH    (DDIM / KCH)

#define COEF_F ((float)(1.602176634e-19 * 1.602176634e-19 / \
                 (4.0 * 3.14159265358979323846 * 8.8541878128e-12 * 1e-10)))

typedef unsigned long long u64;

// smem layout (dynamic):
//   [0)            Xh[64*LDA] bf16, Xl[64*LDA] bf16          (67,584 B)
//   [SM_BOFF)      B stage0 (h+l), B stage1 (h+l)            (33,792 B)
//                  -- aliased by F[64*LDF] fp32 during epilogues (33,776 B)
#define SM_XL   (64 * LDA)                  // elems per X tile
#define SM_BOFF (2 * SM_XL * 2)             // 67,584 bytes
#define SM_BSTG (2 * KCH * LDB * 2)         // 16,896 bytes per stage (h+l)
#define SMEM_W  (SM_BOFF + 2 * SM_BSTG)     // 101,376 bytes

// ---- scratch (static device globals; no allocation) ----
__device__ float d_dist[NEDGES];
__device__ float d_h   [NATOMS * DDIM];
__device__ float d_hsrc[NATOMS * DDIM];
__device__ float d_hdst[NATOMS * DDIM];
__device__ float d_agg [NATOMS * DDIM];
__device__ float d_pool[NGRAPH];
__device__ int   d_cnt [NGRAPH];

// bf16-split weights, prepped once per launch. [L*4][256][256] row-major (k, n)
#define WELEMS (LLAYERS * 4 * DDIM * DDIM)
__device__ __align__(256) __nv_bfloat16 d_w1h[WELEMS];
__device__ __align__(256) __nv_bfloat16 d_w1l[WELEMS];
__device__ __align__(256) __nv_bfloat16 d_w2h[WELEMS];
__device__ __align__(256) __nv_bfloat16 d_w2l[WELEMS];

// ---- helpers ----
__device__ __forceinline__ void bsplit(float v, __nv_bfloat16& h, __nv_bfloat16& l) {
    h = __float2bfloat16(v);
    l = __float2bfloat16(v - __bfloat162float(h));
}
__device__ __forceinline__ void red2(float* p, float a, float b) {
    asm volatile("red.global.add.v2.f32 [%0], {%1, %2};" :: "l"(p), "f"(a), "f"(b) : "memory");
}
__device__ __forceinline__ float softplus_f(float x) {
    return fmaxf(x, 0.0f) + __logf(1.0f + __expf(-fabsf(x)));
}
__device__ __forceinline__ float mish_f(float x) {
    float ex = __expf(fminf(x, 20.0f));
    float p  = 1.0f + ex;
    float p2 = p * p;
    return x * __fdividef(p2 - 1.0f, p2 + 1.0f);
}

__device__ __forceinline__ void cpa16(unsigned saddr, const void* gptr) {
    asm volatile("cp.async.cg.shared.global [%0], [%1], 16;" :: "r"(saddr), "l"(gptr));
}
#define CP_COMMIT() asm volatile("cp.async.commit_group;" ::: "memory")
__device__ __forceinline__ void cp_wait1() { asm volatile("cp.async.wait_group 1;" ::: "memory"); }
__device__ __forceinline__ void cp_wait0() { asm volatile("cp.async.wait_group 0;" ::: "memory"); }

// ---- weight prep: fp32 -> (hi, lo) bf16 split ----
__global__ void __launch_bounds__(256) prep_w(const float* __restrict__ cw1,
                                              const float* __restrict__ cw2) {
    int i = blockIdx.x * blockDim.x + threadIdx.x;
    if (i < WELEMS) {
        __nv_bfloat16 h, l;
        bsplit(cw1[i], h, l); d_w1h[i] = h; d_w1l[i] = l;
        bsplit(cw2[i], h, l); d_w2h[i] = h; d_w2l[i] = l;
    }
}

// ---- async B chunk load: 16 rows x 256 cols, h+l halves, 64B per thread ----
__device__ __forceinline__ void ldB_async(unsigned sB, const __nv_bfloat16* __restrict__ gWh,
                                          const __nv_bfloat16* __restrict__ gWl,
                                          int k0, int tid) {
    int rr = tid >> 4;             // 0..15
    int cb = (tid & 15) * 16;      // 0,16,..,240 (bf16 elems)
    unsigned dsth = sB + (unsigned)(rr * LDB + cb) * 2;
    unsigned dstl = dsth + KCH * LDB * 2;
    const __nv_bfloat16* sh = gWh + (size_t)(k0 + rr) * DDIM + cb;
    const __nv_bfloat16* sl = gWl + (size_t)(k0 + rr) * DDIM + cb;
    cpa16(dsth, sh);      cpa16(dsth + 16, sh + 8);
    cpa16(dstl, sl);      cpa16(dstl + 16, sl + 8);
}

// ---- pipelined wmma GEMM: D[64,256] = X[64,256] @ W[256,256], 3-pass bf16 split ----
__device__ __forceinline__ void wgemm(
    const __nv_bfloat16* __restrict__ gWh, const __nv_bfloat16* __restrict__ gWl,
    const __nv_bfloat16* sXh, const __nv_bfloat16* sXl, char* smem,
    wmma::fragment<wmma::accumulator, 16, 16, 16, float>* acc,
    int tid, int mw, int nh) {
#pragma unroll
    for (int f = 0; f < 8; f++) wmma::fill_fragment(acc[f], 0.0f);
    __nv_bfloat16* sB0 = (__nv_bfloat16*)(smem + SM_BOFF);
    __nv_bfloat16* sB1 = (__nv_bfloat16*)(smem + SM_BOFF + SM_BSTG);
    unsigned a0 = (unsigned)__cvta_generic_to_shared(sB0);
    unsigned a1 = (unsigned)__cvta_generic_to_shared(sB1);
    ldB_async(a0, gWh, gWl, 0, tid);
    CP_COMMIT();
    for (int c = 0; c < NCH; c++) {
        __syncthreads();               // all warps done with the buffer we're about to refill
        if (c < NCH - 1) ldB_async((c & 1) ? a0 : a1, gWh, gWl, (c + 1) * KCH, tid);
        CP_COMMIT();
        if (c < NCH - 1) cp_wait1(); else cp_wait0();
        __syncthreads();               // chunk c visible to all warps
        const __nv_bfloat16* bh_base = (c & 1) ? sB1 : sB0;
        const __nv_bfloat16* bl_base = bh_base + KCH * LDB;
        wmma::fragment<wmma::matrix_a, 16, 16, 16, __nv_bfloat16, wmma::row_major> ah, al;
        wmma::load_matrix_sync(ah, sXh + mw * 16 * LDA + c * KCH, LDA);
        wmma::load_matrix_sync(al, sXl + mw * 16 * LDA + c * KCH, LDA);
#pragma unroll
        for (int f = 0; f < 8; f++) {
            wmma::fragment<wmma::matrix_b, 16, 16, 16, __nv_bfloat16, wmma::row_major> bh, bl;
            wmma::load_matrix_sync(bh, bh_base + nh * 128 + f * 16, LDB);
            wmma::load_matrix_sync(bl, bl_base + nh * 128 + f * 16, LDB);
            wmma::mma_sync(acc[f], ah, bh, acc[f]);
            wmma::mma_sync(acc[f], ah, bl, acc[f]);
            wmma::mma_sync(acc[f], al, bh, acc[f]);
        }
    }
    __syncthreads();                   // B dead; F may alias it now
}

// Stage one 128-col half into fp32 staging (aliases B region); returns sF.
__device__ __forceinline__ float* stage_half(
    char* smem, wmma::fragment<wmma::accumulator, 16, 16, 16, float>* acc,
    int q, int mw, int nh) {
    float* sF = (float*)(smem + SM_BOFF);
    if (nh == q) {
#pragma unroll
        for (int f = 0; f < 8; f++)
            wmma::store_matrix_sync(sF + mw * 16 * LDF + f * 16, acc[f],
                                    LDF, wmma::mem_row_major);
    }
    __syncthreads();
    return sF;
}

// ---- small kernels ----
__global__ void __launch_bounds__(256) dist_kernel(const float* __restrict__ r) {
    int e = blockIdx.x * blockDim.x + threadIdx.x;
    if (e < NEDGES) {
        float x = r[3 * e], y = r[3 * e + 1], z = r[3 * e + 2];
        d_dist[e] = sqrtf(x * x + y * y + z * z);
    }
}

__global__ void __launch_bounds__(256) zero_pool_kernel() {
    int g = blockIdx.x * blockDim.x + threadIdx.x;
    if (g < NGRAPH) { d_pool[g] = 0.0f; d_cnt[g] = 0; }
}

__global__ void __launch_bounds__(256) pool_kernel(const int* __restrict__ gids,
                                                   const float* __restrict__ out_w) {
    int warp = (blockIdx.x * blockDim.x + threadIdx.x) >> 5;
    int lane = threadIdx.x & 31;
    if (warp >= NATOMS) return;
    float s = 0.0f;
    for (int k = lane; k < DDIM; k += 32) {
        size_t off = (size_t)warp * DDIM + k;
        s += softplus_f(d_h[off] + d_agg[off]) * out_w[k];
    }
#pragma unroll
    for (int off = 16; off > 0; off >>= 1)
        s += __shfl_xor_sync(0xFFFFFFFFu, s, off);
    if (lane == 0) {
        atomicAdd(&d_pool[gids[warp]], s);
        atomicAdd(&d_cnt[gids[warp]], 1);
    }
}

__global__ void __launch_bounds__(256) final_kernel(const float* __restrict__ out_b,
                                                    float* __restrict__ out) {
    int g = blockIdx.x * blockDim.x + threadIdx.x;
    if (g < NGRAPH)
        out[g] = d_pool[g] / fmaxf((float)d_cnt[g], 1.0f) + out_b[0];
}

// ==== scalar embed path (proven; off critical path) ====
#define ETE   32
#define ENT   128
#define EPADR 36
#define KEMB  224
__device__ __forceinline__ u64 pack2f(float lo, float hi) {
    u64 v; asm("mov.b64 %0, {%1, %2};" : "=l"(v) : "f"(lo), "f"(hi)); return v;
}
__device__ __forceinline__ void unpack2f(u64 v, float& lo, float& hi) {
    asm("mov.b64 {%0, %1}, %2;" : "=f"(lo), "=f"(hi) : "l"(v));
}
__device__ __forceinline__ void fma2(u64& a, u64 x, u64 w) {
    asm("fma.rn.f32x2 %0, %1, %2, %0;" : "+l"(a) : "l"(x), "l"(w));
}
__device__ __forceinline__ void eldw4c(float2 w[4][2], const float* __restrict__ W,
                                       int k, int cp, int kmax) {
#pragma unroll
    for (int i = 0; i < 4; i++) {
        int kk = k + i; if (kk >= kmax) kk = kmax - 1;
        w[i][0] = *(const float2*)(W + (size_t)kk * DDIM + 2 * cp);
        w[i][1] = *(const float2*)(W + (size_t)kk * DDIM + 2 * cp + 128);
    }
}
__device__ __forceinline__ void eldx(ulonglong2 cur[4], const float* __restrict__ xs, int k) {
    const ulonglong2* xr = (const ulonglong2*)(xs + (size_t)k * EPADR);
#pragma unroll
    for (int j = 0; j < 4; j++) cur[j] = xr[j];
}
__device__ __forceinline__ void efma_k(u64 acc[32], float2 w01, float2 w23,
                                       const ulonglong2 cur[4]) {
    u64 wv0 = pack2f(w01.x, w01.x), wv1 = pack2f(w01.y, w01.y);
    u64 wv2 = pack2f(w23.x, w23.x), wv3 = pack2f(w23.y, w23.y);
#pragma unroll
    for (int j2 = 0; j2 < 4; j2++) {
        u64 plo = cur[j2].x, phi = cur[j2].y;
        fma2(acc[     2 * j2], plo, wv0); fma2(acc[     2 * j2 + 1], phi, wv0);
        fma2(acc[ 8 + 2 * j2], plo, wv1); fma2(acc[ 8 + 2 * j2 + 1], phi, wv1);
        fma2(acc[16 + 2 * j2], plo, wv2); fma2(acc[16 + 2 * j2 + 1], phi, wv2);
        fma2(acc[24 + 2 * j2], plo, wv3); fma2(acc[24 + 2 * j2 + 1], phi, wv3);
    }
}
__global__ void __launch_bounds__(ENT) embed_kernel(const int* __restrict__ atom_types,
                                                    const float* __restrict__ af,
                                                    const float* __restrict__ emb_w,
                                                    const float* __restrict__ emb_b) {
    extern __shared__ float esm[];
    float* xa = esm;
    __shared__ int sT[ETE];
    int tid = threadIdx.x;
    int cp = tid & 63, rg = tid >> 6, rbase = rg * 16;
    int row0 = blockIdx.x * ETE;
    if (tid < ETE) {
        int row = row0 + tid;
        sT[tid] = (row < NATOMS) ? atom_types[row] : 0;
    }
    __syncthreads();
    for (int idx = tid; idx < ETE * KEMB; idx += ENT) {
        int r = idx / KEMB, k = idx - r * KEMB;
        float v = 0.0f;
        if (k < ADIM && row0 + r < NATOMS) v = af[(size_t)sT[r] * ADIM + k];
        xa[k * EPADR + r] = v;
    }
    __syncthreads();
    u64 acc[32];
#pragma unroll
    for (int j = 0; j < 32; j++) acc[j] = 0ULL;
    {
        const float* xs = xa + rbase;
        float2 wa[4][2], wb[4][2];
        ulonglong2 cur[4], nxt[4];
        eldw4c(wa, emb_w, 0, cp, ADIM);
        eldx(cur, xs, 0);
        for (int k0 = 0; k0 < KEMB; k0 += 8) {
            eldw4c(wb, emb_w, k0 + 4, cp, ADIM);
#pragma unroll
            for (int i = 0; i < 4; i++) {
                int kk = k0 + i + 1; if (kk >= KEMB) kk = 0;
                eldx(nxt, xs, kk);
                efma_k(acc, wa[i][0], wa[i][1], cur);
#pragma unroll
                for (int j = 0; j < 4; j++) cur[j] = nxt[j];
            }
            eldw4c(wa, emb_w, (k0 + 8 < KEMB) ? k0 + 8 : 0, cp, ADIM);
#pragma unroll
            for (int i = 0; i < 4; i++) {
                int kk = k0 + 5 + i; if (kk >= KEMB) kk = 0;
                eldx(nxt, xs, kk);
                efma_k(acc, wb[i][0], wb[i][1], cur);
#pragma unroll
                for (int j = 0; j < 4; j++) cur[j] = nxt[j];
            }
        }
    }
    float2 b01 = *(const float2*)(emb_b + 2 * cp);
    float2 b23 = *(const float2*)(emb_b + 2 * cp + 128);
#pragma unroll
    for (int j = 0; j < 8; j++) {
        float lo0, hi0, lo1, hi1, lo2, hi2, lo3, hi3;
        unpack2f(acc[j],      lo0, hi0);
        unpack2f(acc[8 + j],  lo1, hi1);
        unpack2f(acc[16 + j], lo2, hi2);
        unpack2f(acc[24 + j], lo3, hi3);
        int r0 = row0 + rbase + 2 * j, r1 = r0 + 1;
        if (r0 < NATOMS) {
            *(float2*)(d_h + (size_t)r0 * DDIM + 2 * cp)       = make_float2(lo0 + b01.x, lo1 + b01.y);
            *(float2*)(d_h + (size_t)r0 * DDIM + 2 * cp + 128) = make_float2(lo2 + b23.x, lo3 + b23.y);
        }
        if (r1 < NATOMS) {
            *(float2*)(d_h + (size_t)r1 * DDIM + 2 * cp)       = make_float2(hi0 + b01.x, hi1 + b01.y);
            *(float2*)(d_h + (size_t)r1 * DDIM + 2 * cp + 128) = make_float2(hi2 + b23.x, hi3 + b23.y);
        }
    }
}

// ==== wmma node kernel ====
__global__ void __launch_bounds__(NT, 2) node_kernel_w(
    int l, int use_agg, const float* __restrict__ cb1, const float* __restrict__ cb2) {
    extern __shared__ char smem[];
    __nv_bfloat16* sXh = (__nv_bfloat16*)smem;
    __nv_bfloat16* sXl = sXh + SM_XL;
    int tid = threadIdx.x;
    int wid = tid >> 5, mw = wid & 3, nh = wid >> 2;
    int row0 = blockIdx.x * TE;

    const size_t MM = (size_t)DDIM * DDIM;
    const __nv_bfloat16 *w1sh = d_w1h + (size_t)(l * 4 + 0) * MM, *w1sl = d_w1l + (size_t)(l * 4 + 0) * MM;
    const __nv_bfloat16 *w2sh = d_w2h + (size_t)(l * 4 + 0) * MM, *w2sl = d_w2l + (size_t)(l * 4 + 0) * MM;
    const __nv_bfloat16 *w1dh = d_w1h + (size_t)(l * 4 + 1) * MM, *w1dl = d_w1l + (size_t)(l * 4 + 1) * MM;
    const __nv_bfloat16 *w2dh = d_w2h + (size_t)(l * 4 + 1) * MM, *w2dl = d_w2l + (size_t)(l * 4 + 1) * MM;
    const float *b1s = cb1 + (l * 4 + 0) * DDIM, *b2s = cb2 + (l * 4 + 0) * DDIM;
    const float *b1d = cb1 + (l * 4 + 1) * DDIM, *b2d = cb2 + (l * 4 + 1) * DDIM;

    // load h tile (+ fused softplus/agg-zero), split to bf16
    for (int i = tid; i < TE * DDIM; i += NT) {
        int r = i >> 8, c = i & 255;
        int row = row0 + r;
        float v = 0.0f;
        if (row < NATOMS) {
            size_t off = (size_t)row * DDIM + c;
            if (use_agg) { v = softplus_f(d_h[off] + d_agg[off]); d_h[off] = v; }
            else v = d_h[off];
            d_agg[off] = 0.0f;
        }
        __nv_bfloat16 h, lo; bsplit(v, h, lo);
        sXh[r * LDA + c] = h; sXl[r * LDA + c] = lo;
    }
    // (wgemm's first barrier makes X visible)

    wmma::fragment<wmma::accumulator, 16, 16, 16, float> acc[8];

    // src branch
    wgemm(w1sh, w1sl, sXh, sXl, smem, acc, tid, mw, nh);
    for (int q = 0; q < 2; q++) {
        float* sF = stage_half(smem, acc, q, mw, nh);
        for (int i = tid; i < 64 * 128; i += NT) {
            int r = i >> 7, c = i & 127; int C = q * 128 + c;
            float v = mish_f(sF[r * LDF + c] + b1s[C]);
            __nv_bfloat16 h, lo; bsplit(v, h, lo);
            sXh[r * LDA + C] = h; sXl[r * LDA + C] = lo;
        }
        __syncthreads();
    }
    wgemm(w2sh, w2sl, sXh, sXl, smem, acc, tid, mw, nh);
    for (int q = 0; q < 2; q++) {
        float* sF = stage_half(smem, acc, q, mw, nh);
        for (int i = tid; i < 64 * 128; i += NT) {
            int r = i >> 7, c = i & 127; int C = q * 128 + c;
            int row = row0 + r;
            if (row < NATOMS) d_hsrc[(size_t)row * DDIM + C] = sF[r * LDF + c] + b2s[C];
        }
        __syncthreads();
    }

    // reload h for dst branch
    for (int i = tid; i < TE * DDIM; i += NT) {
        int r = i >> 8, c = i & 255;
        int row = row0 + r;
        float v = (row < NATOMS) ? d_h[(size_t)row * DDIM + c] : 0.0f;
        __nv_bfloat16 h, lo; bsplit(v, h, lo);
        sXh[r * LDA + c] = h; sXl[r * LDA + c] = lo;
    }
    wgemm(w1dh, w1dl, sXh, sXl, smem, acc, tid, mw, nh);
    for (int q = 0; q < 2; q++) {
        float* sF = stage_half(smem, acc, q, mw, nh);
        for (int i = tid; i < 64 * 128; i += NT) {
            int r = i >> 7, c = i & 127; int C = q * 128 + c;
            float v = mish_f(sF[r * LDF + c] + b1d[C]);
            __nv_bfloat16 h, lo; bsplit(v, h, lo);
            sXh[r * LDA + C] = h; sXl[r * LDA + C] = lo;
        }
        __syncthreads();
    }
    wgemm(w2dh, w2dl, sXh, sXl, smem, acc, tid, mw, nh);
    for (int q = 0; q < 2; q++) {
        float* sF = stage_half(smem, acc, q, mw, nh);
        for (int i = tid; i < 64 * 128; i += NT) {
            int r = i >> 7, c = i & 127; int C = q * 128 + c;
            int row = row0 + r;
            if (row < NATOMS) d_hdst[(size_t)row * DDIM + C] = sF[r * LDF + c] + b2d[C];
        }
        __syncthreads();
    }
}

// ==== wmma edge kernel: RBF -> eMLP -> combine -> mMLP -> scatter ====
__global__ void __launch_bounds__(NT, 2) edge_kernel_w(
    const int* __restrict__ esrc, const int* __restrict__ edst, int l,
    const float* __restrict__ cb1, const float* __restrict__ cb2) {
    extern __shared__ char smem[];
    __nv_bfloat16* sXh = (__nv_bfloat16*)smem;
    __nv_bfloat16* sXl = sXh + SM_XL;
    __shared__ int   sS[TE], sD[TE];
    __shared__ float sDist[TE];
    int tid = threadIdx.x;
    int wid = tid >> 5, mw = wid & 3, nh = wid >> 2;
    int e0 = blockIdx.x * TE;

    const size_t MM = (size_t)DDIM * DDIM;
    const __nv_bfloat16 *w1eh = d_w1h + (size_t)(l * 4 + 2) * MM, *w1el = d_w1l + (size_t)(l * 4 + 2) * MM;
    const __nv_bfloat16 *w2eh = d_w2h + (size_t)(l * 4 + 2) * MM, *w2el = d_w2l + (size_t)(l * 4 + 2) * MM;
    const __nv_bfloat16 *w1mh = d_w1h + (size_t)(l * 4 + 3) * MM, *w1ml = d_w1l + (size_t)(l * 4 + 3) * MM;
    const __nv_bfloat16 *w2mh = d_w2h + (size_t)(l * 4 + 3) * MM, *w2ml = d_w2l + (size_t)(l * 4 + 3) * MM;
    const float *b1e = cb1 + (l * 4 + 2) * DDIM, *b2e = cb2 + (l * 4 + 2) * DDIM;
    const float *b1m = cb1 + (l * 4 + 3) * DDIM, *b2m = cb2 + (l * 4 + 3) * DDIM;

    if (tid < TE) {
        int e = e0 + tid;
        sS[tid]    = (e < NEDGES) ? esrc[e] : 0;
        sD[tid]    = (e < NEDGES) ? edst[e] : 0;
        sDist[tid] = (e < NEDGES) ? d_dist[e] : 0.0f;
    }
    __syncthreads();

    // RBF -> X (bf16 split)
    for (int i = tid; i < TE * DDIM; i += NT) {
        int r = i >> 8, c = i & 255;
        float t = sDist[r] - (float)c * (1.0f / 255.0f);
        float v = __expf(-255.0f * t * t);
        __nv_bfloat16 h, lo; bsplit(v, h, lo);
        sXh[r * LDA + c] = h; sXl[r * LDA + c] = lo;
    }

    wmma::fragment<wmma::accumulator, 16, 16, 16, float> acc[8];

    // edge MLP layer 1: mish -> X
    wgemm(w1eh, w1el, sXh, sXl, smem, acc, tid, mw, nh);
    for (int q = 0; q < 2; q++) {
        float* sF = stage_half(smem, acc, q, mw, nh);
        for (int i = tid; i < 64 * 128; i += NT) {
            int r = i >> 7, c = i & 127; int C = q * 128 + c;
            float v = mish_f(sF[r * LDF + c] + b1e[C]);
            __nv_bfloat16 h, lo; bsplit(v, h, lo);
            sXh[r * LDA + C] = h; sXl[r * LDA + C] = lo;
        }
        __syncthreads();
    }

    // edge MLP layer 2 + Coulomb combine -> X
    wgemm(w2eh, w2el, sXh, sXl, smem, acc, tid, mw, nh);
    for (int q = 0; q < 2; q++) {
        float* sF = stage_half(smem, acc, q, mw, nh);
        for (int i = tid; i < 64 * 64; i += NT) {
            int r = i >> 6, c2 = i & 63; int C = q * 128 + 2 * c2;
            float el0 = sF[r * LDF + 2 * c2]     + b2e[C];
            float el1 = sF[r * LDF + 2 * c2 + 1] + b2e[C + 1];
            float2 hs = *(const float2*)(d_hsrc + (size_t)sS[r] * DDIM + C);
            float2 hd = *(const float2*)(d_hdst + (size_t)sD[r] * DDIM + C);
            float v0 = __fdividef(hs.x * hd.x * COEF_F, el0);
            float v1 = __fdividef(hs.y * hd.y * COEF_F, el1);
            __nv_bfloat16 h, lo;
            bsplit(v0, h, lo); sXh[r * LDA + C] = h;     sXl[r * LDA + C] = lo;
            bsplit(v1, h, lo); sXh[r * LDA + C + 1] = h; sXl[r * LDA + C + 1] = lo;
        }
        __syncthreads();
    }

    // m MLP layer 1: mish -> X
    wgemm(w1mh, w1ml, sXh, sXl, smem, acc, tid, mw, nh);
    for (int q = 0; q < 2; q++) {
        float* sF = stage_half(smem, acc, q, mw, nh);
        for (int i = tid; i < 64 * 128; i += NT) {
            int r = i >> 7, c = i & 127; int C = q * 128 + c;
            float v = mish_f(sF[r * LDF + c] + b1m[C]);
            __nv_bfloat16 h, lo; bsplit(v, h, lo);
            sXh[r * LDA + C] = h; sXl[r * LDA + C] = lo;
        }
        __syncthreads();
    }

    // m MLP layer 2 + segment-sum scatter
    wgemm(w2mh, w2ml, sXh, sXl, smem, acc, tid, mw, nh);
    for (int q = 0; q < 2; q++) {
        float* sF = stage_half(smem, acc, q, mw, nh);
        for (int i = tid; i < 64 * 64; i += NT) {
            int r = i >> 6, c2 = i & 63; int C = q * 128 + 2 * c2;
            if (e0 + r < NEDGES) {
                float v0 = sF[r * LDF + 2 * c2]     + b2m[C];
                float v1 = sF[r * LDF + 2 * c2 + 1] + b2m[C + 1];
                red2(d_agg + (size_t)sD[r] * DDIM + C, v0, v1);
            }
        }
        __syncthreads();
    }
}

extern "C" void kernel_launch(void* const* d_in, const int* in_sizes, int n_in,
                              void* d_out, int out_size) {
    const int*   atom_types = (const int*)  d_in[0];
    const int*   esrc       = (const int*)  d_in[1];
    const int*   edst       = (const int*)  d_in[2];
    const int*   gids       = (const int*)  d_in[3];
    const float* r          = (const float*)d_in[4];
    const float* af         = (const float*)d_in[5];
    const float* emb_w      = (const float*)d_in[6];
    const float* emb_b      = (const float*)d_in[7];
    const float* cw1        = (const float*)d_in[8];
    const float* cb1        = (const float*)d_in[9];
    const float* cw2        = (const float*)d_in[10];
    const float* cb2        = (const float*)d_in[11];
    const float* out_w      = (const float*)d_in[12];
    const float* out_b      = (const float*)d_in[13];
    float* out = (float*)d_out;

    const int SMEM_EMBED = KEMB * EPADR * 4;
    cudaFuncSetAttribute(edge_kernel_w, cudaFuncAttributeMaxDynamicSharedMemorySize, SMEM_W);
    cudaFuncSetAttribute(node_kernel_w, cudaFuncAttributeMaxDynamicSharedMemorySize, SMEM_W);
    cudaFuncSetAttribute(embed_kernel,  cudaFuncAttributeMaxDynamicSharedMemorySize, SMEM_EMBED);

    dist_kernel<<<(NEDGES + 255) / 256, 256>>>(r);
    prep_w<<<(WELEMS + 255) / 256, 256>>>(cw1, cw2);
    embed_kernel<<<(NATOMS + ETE - 1) / ETE, ENT, SMEM_EMBED>>>(atom_types, af, emb_w, emb_b);

    for (int l = 0; l < LLAYERS; l++) {
        node_kernel_w<<<(NATOMS + TE - 1) / TE, NT, SMEM_W>>>(l, l > 0 ? 1 : 0, cb1, cb2);
        edge_kernel_w<<<(NEDGES + TE - 1) / TE, NT, SMEM_W>>>(esrc, edst, l, cb1, cb2);
    }

    zero_pool_kernel<<<(NGRAPH + 255) / 256, 256>>>();
    pool_kernel<<<(NATOMS * 32 + 255) / 256, 256>>>(gids, out_w);
    final_kernel<<<(NGRAPH + 255) / 256, 256>>>(out_b, out);
}